// round 6
// baseline (speedup 1.0000x reference)
#include <cuda_runtime.h>
#include <math.h>
#include <stdint.h>

// ---------------- problem constants ----------------
#define IN_DIM     768
#define DIM        512
#define NUM_BINS   16
#define SEQ_N      2048
#define DAY_LENGTH 64

// ---------------- tiling ----------------
#define BM       128
#define BN       256
#define BK       32
#define STAGES   3
#define NTHREADS 512
#define KTILES   (IN_DIM / BK)        // 24

// warp tiling: 16 warps, 4 (M) x 4 (N), each 32x64
#define MT 2                          // 2 x m16
#define NT 8                          // 8 x n8

// padded smem strides (floats): stride 36 -> fragment LDS banks = 4r+c (conflict-free)
#define AS_STRIDE 36
#define BS_STRIDE 36
#define A_STAGE_FLOATS (BM * AS_STRIDE)              // 4608
#define B_STAGE_FLOATS (BN * BS_STRIDE)              // 9216
#define STAGE_FLOATS   (A_STAGE_FLOATS + B_STAGE_FLOATS)
#define SMEM_BYTES     (STAGES * STAGE_FLOATS * 4)   // 165888

__device__ __forceinline__ uint32_t smem_u32(const void* p) {
    uint32_t a;
    asm("{ .reg .u64 t; cvta.to.shared.u64 t, %1; cvt.u32.u64 %0, t; }" : "=r"(a) : "l"(p));
    return a;
}
__device__ __forceinline__ void cp16(uint32_t dst, const void* src) {
    asm volatile("cp.async.cg.shared.global [%0], [%1], 16;" :: "r"(dst), "l"(src) : "memory");
}

__device__ __forceinline__ void mma_tf32(float* c, const uint32_t* a, const uint32_t* b) {
    asm volatile(
        "mma.sync.aligned.m16n8k8.row.col.f32.tf32.tf32.f32 "
        "{%0,%1,%2,%3}, {%4,%5,%6,%7}, {%8,%9}, {%0,%1,%2,%3};"
        : "+f"(c[0]), "+f"(c[1]), "+f"(c[2]), "+f"(c[3])
        : "r"(a[0]), "r"(a[1]), "r"(a[2]), "r"(a[3]), "r"(b[0]), "r"(b[1]));
}

// ---------------- kernel ----------------
__global__ __launch_bounds__(NTHREADS, 1)
void atom_mma_kernel(const float* __restrict__ x,        // [M, IN_DIM]
                     const float* __restrict__ freqs,    // [DIM, IN_DIM]
                     const float* __restrict__ phase,    // [DIM]
                     const float* __restrict__ heights,  // [DIM, NUM_BINS]
                     const float* __restrict__ bias,     // [DIM]
                     const int*   __restrict__ offset_p,
                     float*       __restrict__ out)      // [M, DIM]
{
    extern __shared__ float smem[];
    const uint32_t sbase = smem_u32(smem);
    const int tid  = threadIdx.x;
    const int wid  = tid >> 5;
    const int lane = tid & 31;
    const int wm   = wid & 3;          // warp M index (0..3), 4 x 32 = 128
    const int wn   = wid >> 2;         // warp N index (0..3), 4 x 64 = 256
    const int f0   = blockIdx.x * BN;
    const int m0   = blockIdx.y * BM;

    const int lr = lane >> 2;          // 0..7
    const int lc = lane & 3;           // 0..3

    float acc[MT][NT][4];
    #pragma unroll
    for (int i = 0; i < MT; i++)
        #pragma unroll
        for (int j = 0; j < NT; j++)
            #pragma unroll
            for (int q = 0; q < 4; q++) acc[i][j][q] = 0.0f;

    // ---- async stage loader (512 threads) ----
    auto load_stage = [&](int s, int kc) {
        const uint32_t abase = sbase + (uint32_t)s * (STAGE_FLOATS * 4);
        const float* ag = x + (size_t)m0 * IN_DIM + kc * BK;
        #pragma unroll
        for (int j = 0; j < 2; j++) {          // A: 128 rows x 8 16B-chunks = 1024
            int idx = tid + j * NTHREADS;
            int row = idx >> 3, c4 = idx & 7;
            cp16(abase + row * (AS_STRIDE * 4) + c4 * 16,
                 ag + (size_t)row * IN_DIM + c4 * 4);
        }
        const uint32_t bbase = abase + A_STAGE_FLOATS * 4;
        const float* bg = freqs + (size_t)f0 * IN_DIM + kc * BK;
        #pragma unroll
        for (int j = 0; j < 4; j++) {          // B: 256 rows x 8 16B-chunks = 2048
            int idx = tid + j * NTHREADS;
            int row = idx >> 3, c4 = idx & 7;
            cp16(bbase + row * (BS_STRIDE * 4) + c4 * 16,
                 bg + (size_t)row * IN_DIM + c4 * 4);
        }
        asm volatile("cp.async.commit_group;" ::: "memory");
    };

    // prologue: stages 0,1
    load_stage(0, 0);
    load_stage(1, 1);

    for (int kc = 0; kc < KTILES; kc++) {
        if (kc < KTILES - 1) asm volatile("cp.async.wait_group 1;" ::: "memory");
        else                 asm volatile("cp.async.wait_group 0;" ::: "memory");
        __syncthreads();
        if (kc + 2 < KTILES) load_stage((kc + 2) % STAGES, kc + 2);

        const float* sa = smem + (kc % STAGES) * STAGE_FLOATS;
        const float* sb = sa + A_STAGE_FLOATS;

        #pragma unroll
        for (int kk = 0; kk < 4; kk++) {       // 4 k8-steps per BK=32
            const int kb = kk * 8;
            uint32_t afrag[MT][4], bfrag[NT][2];
            #pragma unroll
            for (int mt = 0; mt < MT; mt++) {
                int r0 = wm * 32 + mt * 16 + lr;
                afrag[mt][0] = __float_as_uint(sa[r0 * AS_STRIDE + kb + lc]);
                afrag[mt][1] = __float_as_uint(sa[(r0 + 8) * AS_STRIDE + kb + lc]);
                afrag[mt][2] = __float_as_uint(sa[r0 * AS_STRIDE + kb + lc + 4]);
                afrag[mt][3] = __float_as_uint(sa[(r0 + 8) * AS_STRIDE + kb + lc + 4]);
            }
            #pragma unroll
            for (int nt = 0; nt < NT; nt++) {
                int c0 = wn * 64 + nt * 8 + lr;
                bfrag[nt][0] = __float_as_uint(sb[c0 * BS_STRIDE + kb + lc]);
                bfrag[nt][1] = __float_as_uint(sb[c0 * BS_STRIDE + kb + lc + 4]);
            }
            #pragma unroll
            for (int mt = 0; mt < MT; mt++)
                #pragma unroll
                for (int nt = 0; nt < NT; nt++)
                    mma_tf32(acc[mt][nt], afrag[mt], bfrag[nt]);
        }
    }
    __syncthreads();

    // ---- build epilogue tables into freed smem ----
    // val(u) = u*S1[bin] - S2[bin] + bias, prefix sums of softplus(heights)
    float2* stab = reinterpret_cast<float2*>(smem);        // [BN][NUM_BINS]
    float*  ptab = smem + BN * NUM_BINS * 2;               // [BN]
    float*  btab = ptab + BN;                              // [BN]
    if (tid < BN) {
        int fg = f0 + tid;                                 // one f per thread
        float s1 = 0.0f, s2 = 0.0f;
        float2* row = stab + tid * NUM_BINS;
        #pragma unroll
        for (int k = 0; k < NUM_BINS; k++) {
            float h  = heights[fg * NUM_BINS + k];
            float wv = (h > 20.0f) ? h : log1pf(expf(h));  // softplus (accurate)
            s1 += wv;
            s2 += (float)k * (1.0f / 15.0f) * wv;
            row[k] = make_float2(s1, s2);
        }
        ptab[tid] = phase[fg];
        btab[tid] = bias[fg];
    }
    __syncthreads();

    // ---- fused epilogue: sin -> sigmoid -> spline -> bias -> RoPE ----
    const int offset = *offset_p;

    #pragma unroll
    for (int mt = 0; mt < MT; mt++) {
        #pragma unroll
        for (int o = 0; o < 2; o++) {
            const int m = m0 + wm * 32 + mt * 16 + o * 8 + lr;
            const int nseq  = m & (SEQ_N - 1);
            const float tf0 = (float)(nseq + offset);
            const float days  = floorf(tf0 * (1.0f / (float)DAY_LENGTH));
            const float hours = tf0 - days * (float)DAY_LENGTH;

            #pragma unroll
            for (int nt = 0; nt < NT; nt++) {
                const int fl = wn * 64 + nt * 8 + lc * 2;  // even local f
                float vv[2];
                #pragma unroll
                for (int e = 0; e < 2; e++) {
                    float basis = acc[mt][nt][o * 2 + e] + ptab[fl + e];
                    float s = __sinf(basis);
                    float u = __fdividef(1.0f, 1.0f + __expf(-s));
                    int bin = (int)(u * 15.0f);
                    bin = bin < 0 ? 0 : (bin > 15 ? 15 : bin);
                    float2 S = stab[(fl + e) * NUM_BINS + bin];
                    vv[e] = fmaf(u, S.x, -S.y) + btab[fl + e];
                }
                // RoPE freqs computed on the fly (keeps register peak in mainloop)
                float hv = (float)(f0 + fl) * (1.0f / (float)DIM);
                float invh = exp2f(-13.287712379549449f * hv);   // 10000^-half
                float invd = exp2f(-16.609640474436812f * hv);   // 100000^-half
                float sn, cs;
                __sincosf(fmaf(hours, invh, days * invd), &sn, &cs);
                float2 o2;
                o2.x = vv[0] * cs - vv[1] * sn;
                o2.y = vv[0] * sn + vv[1] * cs;
                *reinterpret_cast<float2*>(out + (size_t)m * DIM + f0 + fl) = o2;
            }
        }
    }
}

// ---------------- launch ----------------
extern "C" void kernel_launch(void* const* d_in, const int* in_sizes, int n_in,
                              void* d_out, int out_size)
{
    const float* x       = (const float*)d_in[0];
    const float* freqs   = (const float*)d_in[1];
    const float* phase   = (const float*)d_in[2];
    const float* heights = (const float*)d_in[3];
    const float* bias    = (const float*)d_in[4];
    const int*   offset  = (const int*)d_in[5];
    float*       out     = (float*)d_out;

    const int M = in_sizes[0] / IN_DIM;              // 16384

    // Stateless + graph-capture safe (not a stream op).
    cudaFuncSetAttribute(atom_mma_kernel,
                         cudaFuncAttributeMaxDynamicSharedMemorySize, SMEM_BYTES);

    dim3 grid(DIM / BN, M / BM);                     // (2, 128)
    atom_mma_kernel<<<grid, NTHREADS, SMEM_BYTES>>>(x, freqs, phase, heights, bias,
                                                    offset, out);
}

// round 7
// speedup vs baseline: 1.3790x; 1.3790x over previous
#include <cuda_runtime.h>
#include <cuda_bf16.h>
#include <math.h>
#include <stdint.h>

// ---------------- problem constants ----------------
#define IN_DIM     768
#define DIM        512
#define NUM_BINS   16
#define SEQ_N      2048
#define DAY_LENGTH 64
#define M_TOTAL    16384

// ---------------- tiling ----------------
#define BM       128
#define BN       256
#define BK       32            // halves of K per stage
#define STAGES   4
#define NTHREADS 512
#define KTILES   (IN_DIM / BK) // 24

// 16 warps: 4 (M) x 4 (N), warp tile 32x64
#define MT 2                   // 2 x m16
#define NT 8                   // 8 x n8

// smem: bf16 rows of 40 halves (80 B) -> ldmatrix rows hit all 32 banks once
#define ROW_H       40
#define ROW_B       80
#define A_ROWS      BM
#define B_ROWS      BN
#define STAGE_BYTES ((A_ROWS + B_ROWS) * ROW_B)   // 30720
#define SMEM_BYTES  (STAGES * STAGE_BYTES)        // 122880

// bf16 scratch (device globals -- no allocation)
__device__ __align__(16) __nv_bfloat16 g_xb[(size_t)M_TOTAL * IN_DIM];
__device__ __align__(16) __nv_bfloat16 g_fb[(size_t)DIM * IN_DIM];

__device__ __forceinline__ uint32_t smem_u32(const void* p) {
    uint32_t a;
    asm("{ .reg .u64 t; cvta.to.shared.u64 t, %1; cvt.u32.u64 %0, t; }" : "=r"(a) : "l"(p));
    return a;
}
__device__ __forceinline__ void cp16(uint32_t dst, const void* src) {
    asm volatile("cp.async.cg.shared.global [%0], [%1], 16;" :: "r"(dst), "l"(src) : "memory");
}
#define LDSM4(r, addr)                                                          \
    asm volatile("ldmatrix.sync.aligned.m8n8.x4.shared.b16 {%0,%1,%2,%3}, [%4];"\
        : "=r"((r)[0]), "=r"((r)[1]), "=r"((r)[2]), "=r"((r)[3]) : "r"(addr))

__device__ __forceinline__ void mma_bf16(float* c, const uint32_t* a, const uint32_t* b) {
    asm volatile(
        "mma.sync.aligned.m16n8k16.row.col.f32.bf16.bf16.f32 "
        "{%0,%1,%2,%3}, {%4,%5,%6,%7}, {%8,%9}, {%0,%1,%2,%3};"
        : "+f"(c[0]), "+f"(c[1]), "+f"(c[2]), "+f"(c[3])
        : "r"(a[0]), "r"(a[1]), "r"(a[2]), "r"(a[3]), "r"(b[0]), "r"(b[1]));
}

// ---------------- prepass: fp32 -> bf16 ----------------
__global__ void cvt_x_kernel(const float4* __restrict__ src, int n4) {
    int i = blockIdx.x * blockDim.x + threadIdx.x;
    if (i < n4) {
        float4 v = src[i];
        __nv_bfloat162 lo = __floats2bfloat162_rn(v.x, v.y);
        __nv_bfloat162 hi = __floats2bfloat162_rn(v.z, v.w);
        uint2 o;
        o.x = *reinterpret_cast<uint32_t*>(&lo);
        o.y = *reinterpret_cast<uint32_t*>(&hi);
        reinterpret_cast<uint2*>(g_xb)[i] = o;
    }
}
__global__ void cvt_f_kernel(const float4* __restrict__ src, int n4) {
    int i = blockIdx.x * blockDim.x + threadIdx.x;
    if (i < n4) {
        float4 v = src[i];
        __nv_bfloat162 lo = __floats2bfloat162_rn(v.x, v.y);
        __nv_bfloat162 hi = __floats2bfloat162_rn(v.z, v.w);
        uint2 o;
        o.x = *reinterpret_cast<uint32_t*>(&lo);
        o.y = *reinterpret_cast<uint32_t*>(&hi);
        reinterpret_cast<uint2*>(g_fb)[i] = o;
    }
}

// ---------------- main fused kernel ----------------
__global__ __launch_bounds__(NTHREADS, 1)
void atom_bf16_kernel(const float* __restrict__ phase,    // [DIM]
                      const float* __restrict__ heights,  // [DIM, NUM_BINS]
                      const float* __restrict__ bias,     // [DIM]
                      const int*   __restrict__ offset_p,
                      float*       __restrict__ out)      // [M, DIM]
{
    extern __shared__ float smem[];
    const uint32_t sbase = smem_u32(smem);
    const int tid  = threadIdx.x;
    const int wid  = tid >> 5;
    const int lane = tid & 31;
    const int wm   = wid & 3;          // 4 x 32 = 128 M
    const int wn   = wid >> 2;         // 4 x 64 = 256 N
    const int f0   = blockIdx.x * BN;
    const int m0   = blockIdx.y * BM;
    const int lr   = lane >> 2;        // 0..7
    const int lc   = lane & 3;         // 0..3

    // ldmatrix per-lane base offsets (within a stage)
    const int lrow = lane & 7, lmat = lane >> 3;
    const uint32_t a_lane = (uint32_t)((wm * 32 + (lmat & 1) * 8 + lrow) * ROW_B
                                       + ((lmat >> 1) * 8) * 2);
    const uint32_t b_lane = (uint32_t)(A_ROWS * ROW_B
                                       + (wn * 64 + (lmat >> 1) * 8 + lrow) * ROW_B
                                       + ((lmat & 1) * 8) * 2);

    float acc[MT][NT][4];
    #pragma unroll
    for (int i = 0; i < MT; i++)
        #pragma unroll
        for (int j = 0; j < NT; j++)
            #pragma unroll
            for (int q = 0; q < 4; q++) acc[i][j][q] = 0.0f;

    auto load_stage = [&](int s, int kc) {
        const uint32_t base = sbase + (uint32_t)s * STAGE_BYTES;
        const __nv_bfloat16* ag = g_xb + (size_t)m0 * IN_DIM + kc * BK;
        {   // A: 128 rows x 4 chunks of 16B = 512 (one per thread)
            int row = tid >> 2, c = tid & 3;
            cp16(base + row * ROW_B + c * 16, ag + (size_t)row * IN_DIM + c * 8);
        }
        const __nv_bfloat16* bg = g_fb + (size_t)f0 * IN_DIM + kc * BK;
        const uint32_t bbase = base + A_ROWS * ROW_B;
        #pragma unroll
        for (int j = 0; j < 2; j++) {   // B: 256 rows x 4 chunks = 1024
            int idx = tid + j * NTHREADS;
            int row = idx >> 2, c = idx & 3;
            cp16(bbase + row * ROW_B + c * 16, bg + (size_t)row * IN_DIM + c * 8);
        }
        asm volatile("cp.async.commit_group;" ::: "memory");
    };

    load_stage(0, 0);
    load_stage(1, 1);
    load_stage(2, 2);

    for (int kc = 0; kc < KTILES; kc++) {
        if (kc + 2 < KTILES) asm volatile("cp.async.wait_group 2;" ::: "memory");
        else                 asm volatile("cp.async.wait_group 0;" ::: "memory");
        __syncthreads();
        if (kc + 3 < KTILES) load_stage((kc + 3) % STAGES, kc + 3);

        const uint32_t stg = sbase + (uint32_t)(kc % STAGES) * STAGE_BYTES;

        #pragma unroll
        for (int step = 0; step < 2; step++) {      // 2 x k16 per BK=32
            const uint32_t kb2 = step * 32;         // 16 halves = 32 B
            uint32_t afrag[MT][4], bfrag[4][4];
            #pragma unroll
            for (int mt = 0; mt < MT; mt++)
                LDSM4(afrag[mt], stg + a_lane + mt * (16 * ROW_B) + kb2);
            #pragma unroll
            for (int p = 0; p < 4; p++)
                LDSM4(bfrag[p], stg + b_lane + p * (16 * ROW_B) + kb2);
            #pragma unroll
            for (int mt = 0; mt < MT; mt++)
                #pragma unroll
                for (int p = 0; p < 4; p++) {
                    mma_bf16(acc[mt][2 * p + 0], afrag[mt], &bfrag[p][0]);
                    mma_bf16(acc[mt][2 * p + 1], afrag[mt], &bfrag[p][2]);
                }
        }
    }
    __syncthreads();

    // ---- epilogue tables in freed smem ----
    float2* stab = reinterpret_cast<float2*>(smem);        // [BN][NUM_BINS] = 32 KB
    float*  ptab = smem + BN * NUM_BINS * 2;               // [BN]
    float*  btab = ptab + BN;                              // [BN]
    if (tid < BN) {
        int fg = f0 + tid;
        float s1 = 0.0f, s2 = 0.0f;
        float2* row = stab + tid * NUM_BINS;
        #pragma unroll
        for (int k = 0; k < NUM_BINS; k++) {
            float h  = heights[fg * NUM_BINS + k];
            float wv = (h > 20.0f) ? h : log1pf(expf(h));  // softplus
            s1 += wv;
            s2 += (float)k * (1.0f / 15.0f) * wv;
            row[k] = make_float2(s1, s2);
        }
        ptab[tid] = phase[fg];
        btab[tid] = bias[fg];
    }
    __syncthreads();

    // ---- fused epilogue: sin -> sigmoid -> spline -> bias -> RoPE ----
    const int offset = *offset_p;

    #pragma unroll
    for (int mt = 0; mt < MT; mt++) {
        #pragma unroll
        for (int o = 0; o < 2; o++) {
            const int m = m0 + wm * 32 + mt * 16 + o * 8 + lr;
            const int nseq  = m & (SEQ_N - 1);
            const float tf0 = (float)(nseq + offset);
            const float days  = floorf(tf0 * (1.0f / (float)DAY_LENGTH));
            const float hours = tf0 - days * (float)DAY_LENGTH;

            #pragma unroll
            for (int nt = 0; nt < NT; nt++) {
                const int fl = wn * 64 + nt * 8 + lc * 2;  // even local f
                float vv[2];
                #pragma unroll
                for (int e = 0; e < 2; e++) {
                    float basis = acc[mt][nt][o * 2 + e] + ptab[fl + e];
                    float s = __sinf(basis);
                    float u = __fdividef(1.0f, 1.0f + __expf(-s));
                    int bin = (int)(u * 15.0f);
                    bin = bin < 0 ? 0 : (bin > 15 ? 15 : bin);
                    float2 S = stab[(fl + e) * NUM_BINS + bin];
                    vv[e] = fmaf(u, S.x, -S.y) + btab[fl + e];
                }
                float hv = (float)(f0 + fl) * (1.0f / (float)DIM);
                float invh = exp2f(-13.287712379549449f * hv);   // 10000^-half
                float invd = exp2f(-16.609640474436812f * hv);   // 100000^-half
                float sn, cs;
                __sincosf(fmaf(hours, invh, days * invd), &sn, &cs);
                float2 o2;
                o2.x = vv[0] * cs - vv[1] * sn;
                o2.y = vv[0] * sn + vv[1] * cs;
                *reinterpret_cast<float2*>(out + (size_t)m * DIM + f0 + fl) = o2;
            }
        }
    }
}

// ---------------- launch ----------------
extern "C" void kernel_launch(void* const* d_in, const int* in_sizes, int n_in,
                              void* d_out, int out_size)
{
    const float* x       = (const float*)d_in[0];
    const float* freqs   = (const float*)d_in[1];
    const float* phase   = (const float*)d_in[2];
    const float* heights = (const float*)d_in[3];
    const float* bias    = (const float*)d_in[4];
    const int*   offset  = (const int*)d_in[5];
    float*       out     = (float*)d_out;

    const int M = in_sizes[0] / IN_DIM;              // 16384

    const int xn4 = M * IN_DIM / 4;                  // 3,145,728
    const int fn4 = DIM * IN_DIM / 4;                // 98,304
    cvt_x_kernel<<<(xn4 + 255) / 256, 256>>>((const float4*)x, xn4);
    cvt_f_kernel<<<(fn4 + 255) / 256, 256>>>((const float4*)freqs, fn4);

    // Stateless + graph-capture safe (not a stream op).
    cudaFuncSetAttribute(atom_bf16_kernel,
                         cudaFuncAttributeMaxDynamicSharedMemorySize, SMEM_BYTES);

    dim3 grid(DIM / BN, M / BM);                     // (2, 128)
    atom_bf16_kernel<<<grid, NTHREADS, SMEM_BYTES>>>(phase, heights, bias,
                                                     offset, out);
}

// round 8
// speedup vs baseline: 1.4103x; 1.0227x over previous
#include <cuda_runtime.h>
#include <cuda_bf16.h>
#include <math.h>
#include <stdint.h>

// ---------------- problem constants ----------------
#define IN_DIM     768
#define DIM        512
#define NUM_BINS   16
#define SEQ_N      2048
#define DAY_LENGTH 64
#define M_TOTAL    16384

// ---------------- tiling ----------------
#define BM       128
#define BN       256
#define BK       32            // halves of K per stage
#define STAGES   4
#define NTHREADS 512
#define KTILES   (IN_DIM / BK) // 24

// 16 warps: 4 (M) x 4 (N), warp tile 32x64
#define MT 2                   // 2 x m16
#define NT 8                   // 8 x n8

// smem: bf16 rows of 40 halves (80 B) -> ldmatrix rows hit all 32 banks once
#define ROW_H       40
#define ROW_B       80
#define A_ROWS      BM
#define B_ROWS      BN
#define STAGE_BYTES ((A_ROWS + B_ROWS) * ROW_B)   // 30720
#define SMEM_BYTES  (STAGES * STAGE_BYTES)        // 122880

// bf16 scratch (device globals -- no allocation)
__device__ __align__(16) __nv_bfloat16 g_xb[(size_t)M_TOTAL * IN_DIM];
__device__ __align__(16) __nv_bfloat16 g_fb[(size_t)DIM * IN_DIM];

__device__ __forceinline__ uint32_t smem_u32(const void* p) {
    uint32_t a;
    asm("{ .reg .u64 t; cvta.to.shared.u64 t, %1; cvt.u32.u64 %0, t; }" : "=r"(a) : "l"(p));
    return a;
}
__device__ __forceinline__ void cp16(uint32_t dst, const void* src) {
    asm volatile("cp.async.cg.shared.global [%0], [%1], 16;" :: "r"(dst), "l"(src) : "memory");
}
#define LDSM4(r, addr)                                                          \
    asm volatile("ldmatrix.sync.aligned.m8n8.x4.shared.b16 {%0,%1,%2,%3}, [%4];"\
        : "=r"((r)[0]), "=r"((r)[1]), "=r"((r)[2]), "=r"((r)[3]) : "r"(addr))

__device__ __forceinline__ void mma_bf16(float* c, const uint32_t* a, const uint32_t* b) {
    asm volatile(
        "mma.sync.aligned.m16n8k16.row.col.f32.bf16.bf16.f32 "
        "{%0,%1,%2,%3}, {%4,%5,%6,%7}, {%8,%9}, {%0,%1,%2,%3};"
        : "+f"(c[0]), "+f"(c[1]), "+f"(c[2]), "+f"(c[3])
        : "r"(a[0]), "r"(a[1]), "r"(a[2]), "r"(a[3]), "r"(b[0]), "r"(b[1]));
}

// ---------------- merged prepass: fp32 -> bf16 (x then freqs), MLP=4 ----------------
#define CVT_UNROLL 4
__global__ void cvt_kernel(const float4* __restrict__ x,
                           const float4* __restrict__ fr,
                           int xn4, int tot4) {
    int base = blockIdx.x * (blockDim.x * CVT_UNROLL) + threadIdx.x;
    #pragma unroll
    for (int j = 0; j < CVT_UNROLL; j++) {
        int i = base + j * blockDim.x;
        if (i < xn4) {
            float4 v = x[i];
            __nv_bfloat162 lo = __floats2bfloat162_rn(v.x, v.y);
            __nv_bfloat162 hi = __floats2bfloat162_rn(v.z, v.w);
            uint2 o;
            o.x = *reinterpret_cast<uint32_t*>(&lo);
            o.y = *reinterpret_cast<uint32_t*>(&hi);
            reinterpret_cast<uint2*>(g_xb)[i] = o;
        } else if (i < tot4) {
            float4 v = fr[i - xn4];
            __nv_bfloat162 lo = __floats2bfloat162_rn(v.x, v.y);
            __nv_bfloat162 hi = __floats2bfloat162_rn(v.z, v.w);
            uint2 o;
            o.x = *reinterpret_cast<uint32_t*>(&lo);
            o.y = *reinterpret_cast<uint32_t*>(&hi);
            reinterpret_cast<uint2*>(g_fb)[i - xn4] = o;
        }
    }
}

// ---------------- main fused kernel ----------------
__global__ __launch_bounds__(NTHREADS, 1)
void atom_bf16_kernel(const float* __restrict__ phase,    // [DIM]
                      const float* __restrict__ heights,  // [DIM, NUM_BINS]
                      const float* __restrict__ bias,     // [DIM]
                      const int*   __restrict__ offset_p,
                      float*       __restrict__ out)      // [M, DIM]
{
    extern __shared__ float smem[];
    const uint32_t sbase = smem_u32(smem);
    const int tid  = threadIdx.x;
    const int wid  = tid >> 5;
    const int lane = tid & 31;
    const int wm   = wid & 3;          // 4 x 32 = 128 M
    const int wn   = wid >> 2;         // 4 x 64 = 256 N
    const int f0   = blockIdx.x * BN;
    const int m0   = blockIdx.y * BM;
    const int lr   = lane >> 2;        // 0..7
    const int lc   = lane & 3;         // 0..3

    // ldmatrix per-lane base offsets (within a stage)
    const int lrow = lane & 7, lmat = lane >> 3;
    const uint32_t a_lane = (uint32_t)((wm * 32 + (lmat & 1) * 8 + lrow) * ROW_B
                                       + ((lmat >> 1) * 8) * 2);
    const uint32_t b_lane = (uint32_t)(A_ROWS * ROW_B
                                       + (wn * 64 + (lmat >> 1) * 8 + lrow) * ROW_B
                                       + ((lmat & 1) * 8) * 2);

    float acc[MT][NT][4];
    #pragma unroll
    for (int i = 0; i < MT; i++)
        #pragma unroll
        for (int j = 0; j < NT; j++)
            #pragma unroll
            for (int q = 0; q < 4; q++) acc[i][j][q] = 0.0f;

    auto load_stage = [&](int s, int kc) {
        const uint32_t base = sbase + (uint32_t)s * STAGE_BYTES;
        const __nv_bfloat16* ag = g_xb + (size_t)m0 * IN_DIM + kc * BK;
        {   // A: 128 rows x 4 chunks of 16B = 512 (one per thread)
            int row = tid >> 2, c = tid & 3;
            cp16(base + row * ROW_B + c * 16, ag + (size_t)row * IN_DIM + c * 8);
        }
        const __nv_bfloat16* bg = g_fb + (size_t)f0 * IN_DIM + kc * BK;
        const uint32_t bbase = base + A_ROWS * ROW_B;
        #pragma unroll
        for (int j = 0; j < 2; j++) {   // B: 256 rows x 4 chunks = 1024
            int idx = tid + j * NTHREADS;
            int row = idx >> 2, c = idx & 3;
            cp16(bbase + row * ROW_B + c * 16, bg + (size_t)row * IN_DIM + c * 8);
        }
        asm volatile("cp.async.commit_group;" ::: "memory");
    };

    uint32_t af0[MT][4], bf0[4][4];    // step-0 fragment buffers
    uint32_t af1[MT][4], bf1[4][4];    // step-1 fragment buffers

    auto ldsm_all = [&](uint32_t stg, uint32_t kb2, uint32_t (*af)[4], uint32_t (*bf)[4]) {
        #pragma unroll
        for (int mt = 0; mt < MT; mt++)
            LDSM4(af[mt], stg + a_lane + mt * (16 * ROW_B) + kb2);
        #pragma unroll
        for (int p = 0; p < 4; p++)
            LDSM4(bf[p], stg + b_lane + p * (16 * ROW_B) + kb2);
    };
    auto hmma_all = [&](uint32_t (*af)[4], uint32_t (*bf)[4]) {
        #pragma unroll
        for (int mt = 0; mt < MT; mt++)
            #pragma unroll
            for (int p = 0; p < 4; p++) {
                mma_bf16(acc[mt][2 * p + 0], af[mt], &bf[p][0]);
                mma_bf16(acc[mt][2 * p + 1], af[mt], &bf[p][2]);
            }
    };

    // prologue: 3 stages in flight, frags for (kc=0, step0) resident
    load_stage(0, 0);
    load_stage(1, 1);
    load_stage(2, 2);
    asm volatile("cp.async.wait_group 2;" ::: "memory");
    __syncthreads();
    ldsm_all(sbase, 0, af0, bf0);

    for (int kc = 0; kc < KTILES; kc++) {
        const uint32_t stg = sbase + (uint32_t)(kc % STAGES) * STAGE_BYTES;

        // step 0: prefetch step-1 frags, then consume step-0 frags
        ldsm_all(stg, 32, af1, bf1);                    // k16 #1 (32 B offset)
        hmma_all(af0, bf0);

        // stage machinery + cross-kc fragment prefetch (hidden under HMMAs)
        if (kc + 3 < KTILES) {
            load_stage((kc + 3) % STAGES, kc + 3);
            asm volatile("cp.async.wait_group 2;" ::: "memory");
        } else if (kc + 2 < KTILES) {
            asm volatile("cp.async.wait_group 1;" ::: "memory");
        } else if (kc + 1 < KTILES) {
            asm volatile("cp.async.wait_group 0;" ::: "memory");
        }
        if (kc + 1 < KTILES) {
            __syncthreads();                            // stage kc+1 ready & safe
            ldsm_all(sbase + (uint32_t)((kc + 1) % STAGES) * STAGE_BYTES, 0, af0, bf0);
        }

        // step 1: consume step-1 frags
        hmma_all(af1, bf1);
    }
    __syncthreads();

    // ---- epilogue tables in freed smem ----
    float2* stab = reinterpret_cast<float2*>(smem);        // [BN][NUM_BINS] = 32 KB
    float*  ptab = smem + BN * NUM_BINS * 2;               // [BN]
    float*  btab = ptab + BN;                              // [BN]
    if (tid < BN) {
        int fg = f0 + tid;
        float s1 = 0.0f, s2 = 0.0f;
        float2* row = stab + tid * NUM_BINS;
        #pragma unroll
        for (int k = 0; k < NUM_BINS; k++) {
            float h  = heights[fg * NUM_BINS + k];
            float wv = (h > 20.0f) ? h : log1pf(expf(h));  // softplus
            s1 += wv;
            s2 += (float)k * (1.0f / 15.0f) * wv;
            row[k] = make_float2(s1, s2);
        }
        ptab[tid] = phase[fg];
        btab[tid] = bias[fg];
    }
    __syncthreads();

    // ---- fused epilogue: sin -> sigmoid -> spline -> bias -> RoPE ----
    const int offset = *offset_p;

    #pragma unroll
    for (int mt = 0; mt < MT; mt++) {
        #pragma unroll
        for (int o = 0; o < 2; o++) {
            const int m = m0 + wm * 32 + mt * 16 + o * 8 + lr;
            const int nseq  = m & (SEQ_N - 1);
            const float tf0 = (float)(nseq + offset);
            const float days  = floorf(tf0 * (1.0f / (float)DAY_LENGTH));
            const float hours = tf0 - days * (float)DAY_LENGTH;

            #pragma unroll
            for (int nt = 0; nt < NT; nt++) {
                const int fl = wn * 64 + nt * 8 + lc * 2;  // even local f
                float vv[2];
                #pragma unroll
                for (int e = 0; e < 2; e++) {
                    float basis = acc[mt][nt][o * 2 + e] + ptab[fl + e];
                    float s = __sinf(basis);
                    float u = __fdividef(1.0f, 1.0f + __expf(-s));
                    int bin = (int)(u * 15.0f);
                    bin = bin < 0 ? 0 : (bin > 15 ? 15 : bin);
                    float2 S = stab[(fl + e) * NUM_BINS + bin];
                    vv[e] = fmaf(u, S.x, -S.y) + btab[fl + e];
                }
                float hv = (float)(f0 + fl) * (1.0f / (float)DIM);
                float invh = exp2f(-13.287712379549449f * hv);   // 10000^-half
                float invd = exp2f(-16.609640474436812f * hv);   // 100000^-half
                float sn, cs;
                __sincosf(fmaf(hours, invh, days * invd), &sn, &cs);
                float2 o2;
                o2.x = vv[0] * cs - vv[1] * sn;
                o2.y = vv[0] * sn + vv[1] * cs;
                *reinterpret_cast<float2*>(out + (size_t)m * DIM + f0 + fl) = o2;
            }
        }
    }
}

// ---------------- launch ----------------
extern "C" void kernel_launch(void* const* d_in, const int* in_sizes, int n_in,
                              void* d_out, int out_size)
{
    const float* x       = (const float*)d_in[0];
    const float* freqs   = (const float*)d_in[1];
    const float* phase   = (const float*)d_in[2];
    const float* heights = (const float*)d_in[3];
    const float* bias    = (const float*)d_in[4];
    const int*   offset  = (const int*)d_in[5];
    float*       out     = (float*)d_out;

    const int M = in_sizes[0] / IN_DIM;              // 16384

    const int xn4  = M * IN_DIM / 4;                 // 3,145,728
    const int tot4 = xn4 + DIM * IN_DIM / 4;         // +98,304
    const int cvt_blocks = (tot4 + 256 * CVT_UNROLL - 1) / (256 * CVT_UNROLL);
    cvt_kernel<<<cvt_blocks, 256>>>((const float4*)x, (const float4*)freqs, xn4, tot4);

    // Stateless + graph-capture safe (not a stream op).
    cudaFuncSetAttribute(atom_bf16_kernel,
                         cudaFuncAttributeMaxDynamicSharedMemorySize, SMEM_BYTES);

    dim3 grid(DIM / BN, M / BM);                     // (2, 128)
    atom_bf16_kernel<<<grid, NTHREADS, SMEM_BYTES>>>(phase, heights, bias,
                                                     offset, out);
}

// round 9
// speedup vs baseline: 1.4405x; 1.0214x over previous
#include <cuda_runtime.h>
#include <cuda_bf16.h>
#include <math.h>
#include <stdint.h>

// ---------------- problem constants ----------------
#define IN_DIM     768
#define DIM        512
#define NUM_BINS   16
#define SEQ_N      2048
#define DAY_LENGTH 64
#define M_TOTAL    16384

// ---------------- tiling ----------------
#define BM       128
#define BN       256
#define BK       32            // halves of K per stage
#define STAGES   4
#define NTHREADS 256
#define KTILES   (IN_DIM / BK) // 24

// 8 warps: 2 (M) x 4 (N), warp tile 64x64
#define MT 4                   // 4 x m16
#define NT 8                   // 8 x n8

// smem: bf16 rows of 40 halves (80 B) -> ldmatrix rows hit all 32 banks once
#define ROW_H       40
#define ROW_B       80
#define A_ROWS      BM
#define B_ROWS      BN
#define STAGE_BYTES ((A_ROWS + B_ROWS) * ROW_B)   // 30720
#define SMEM_BYTES  (STAGES * STAGE_BYTES)        // 122880

// bf16 scratch (device globals -- no allocation)
__device__ __align__(16) __nv_bfloat16 g_xb[(size_t)M_TOTAL * IN_DIM];
__device__ __align__(16) __nv_bfloat16 g_fb[(size_t)DIM * IN_DIM];

__device__ __forceinline__ uint32_t smem_u32(const void* p) {
    uint32_t a;
    asm("{ .reg .u64 t; cvta.to.shared.u64 t, %1; cvt.u32.u64 %0, t; }" : "=r"(a) : "l"(p));
    return a;
}
__device__ __forceinline__ void cp16(uint32_t dst, const void* src) {
    asm volatile("cp.async.cg.shared.global [%0], [%1], 16;" :: "r"(dst), "l"(src) : "memory");
}
#define LDSM4(r, addr)                                                          \
    asm volatile("ldmatrix.sync.aligned.m8n8.x4.shared.b16 {%0,%1,%2,%3}, [%4];"\
        : "=r"((r)[0]), "=r"((r)[1]), "=r"((r)[2]), "=r"((r)[3]) : "r"(addr))

__device__ __forceinline__ void mma_bf16(float* c, const uint32_t* a, const uint32_t* b) {
    asm volatile(
        "mma.sync.aligned.m16n8k16.row.col.f32.bf16.bf16.f32 "
        "{%0,%1,%2,%3}, {%4,%5,%6,%7}, {%8,%9}, {%0,%1,%2,%3};"
        : "+f"(c[0]), "+f"(c[1]), "+f"(c[2]), "+f"(c[3])
        : "r"(a[0]), "r"(a[1]), "r"(a[2]), "r"(a[3]), "r"(b[0]), "r"(b[1]));
}

// ---------------- merged prepass: fp32 -> bf16 (x then freqs), MLP=4 ----------------
#define CVT_UNROLL 4
__global__ void cvt_kernel(const float4* __restrict__ x,
                           const float4* __restrict__ fr,
                           int xn4, int tot4) {
    int base = blockIdx.x * (blockDim.x * CVT_UNROLL) + threadIdx.x;
    #pragma unroll
    for (int j = 0; j < CVT_UNROLL; j++) {
        int i = base + j * blockDim.x;
        if (i < xn4) {
            float4 v = x[i];
            __nv_bfloat162 lo = __floats2bfloat162_rn(v.x, v.y);
            __nv_bfloat162 hi = __floats2bfloat162_rn(v.z, v.w);
            uint2 o;
            o.x = *reinterpret_cast<uint32_t*>(&lo);
            o.y = *reinterpret_cast<uint32_t*>(&hi);
            reinterpret_cast<uint2*>(g_xb)[i] = o;
        } else if (i < tot4) {
            float4 v = fr[i - xn4];
            __nv_bfloat162 lo = __floats2bfloat162_rn(v.x, v.y);
            __nv_bfloat162 hi = __floats2bfloat162_rn(v.z, v.w);
            uint2 o;
            o.x = *reinterpret_cast<uint32_t*>(&lo);
            o.y = *reinterpret_cast<uint32_t*>(&hi);
            reinterpret_cast<uint2*>(g_fb)[i - xn4] = o;
        }
    }
}

// ---------------- main fused kernel ----------------
__global__ __launch_bounds__(NTHREADS, 1)
void atom_bf16_kernel(const float* __restrict__ phase,    // [DIM]
                      const float* __restrict__ heights,  // [DIM, NUM_BINS]
                      const float* __restrict__ bias,     // [DIM]
                      const int*   __restrict__ offset_p,
                      float*       __restrict__ out)      // [M, DIM]
{
    extern __shared__ float smem[];
    const uint32_t sbase = smem_u32(smem);
    const int tid  = threadIdx.x;
    const int wid  = tid >> 5;
    const int lane = tid & 31;
    const int wm   = wid & 1;          // 2 x 64 = 128 M
    const int wn   = wid >> 1;         // 4 x 64 = 256 N
    const int f0   = blockIdx.x * BN;
    const int m0   = blockIdx.y * BM;
    const int lr   = lane >> 2;        // 0..7
    const int lc   = lane & 3;         // 0..3

    // ldmatrix per-lane base offsets (within a stage)
    const int lrow = lane & 7, lmat = lane >> 3;
    const uint32_t a_lane = (uint32_t)((wm * 64 + (lmat & 1) * 8 + lrow) * ROW_B
                                       + ((lmat >> 1) * 8) * 2);
    const uint32_t b_lane = (uint32_t)(A_ROWS * ROW_B
                                       + (wn * 64 + (lmat >> 1) * 8 + lrow) * ROW_B
                                       + ((lmat & 1) * 8) * 2);

    float acc[MT][NT][4];
    #pragma unroll
    for (int i = 0; i < MT; i++)
        #pragma unroll
        for (int j = 0; j < NT; j++)
            #pragma unroll
            for (int q = 0; q < 4; q++) acc[i][j][q] = 0.0f;

    auto load_stage = [&](int s, int kc) {
        const uint32_t base = sbase + (uint32_t)s * STAGE_BYTES;
        const __nv_bfloat16* ag = g_xb + (size_t)m0 * IN_DIM + kc * BK;
        #pragma unroll
        for (int j = 0; j < 2; j++) {   // A: 128 rows x 4 chunks of 16B = 512
            int idx = tid + j * NTHREADS;
            int row = idx >> 2, c = idx & 3;
            cp16(base + row * ROW_B + c * 16, ag + (size_t)row * IN_DIM + c * 8);
        }
        const __nv_bfloat16* bg = g_fb + (size_t)f0 * IN_DIM + kc * BK;
        const uint32_t bbase = base + A_ROWS * ROW_B;
        #pragma unroll
        for (int j = 0; j < 4; j++) {   // B: 256 rows x 4 chunks = 1024
            int idx = tid + j * NTHREADS;
            int row = idx >> 2, c = idx & 3;
            cp16(bbase + row * ROW_B + c * 16, bg + (size_t)row * IN_DIM + c * 8);
        }
        asm volatile("cp.async.commit_group;" ::: "memory");
    };

    uint32_t af0[MT][4], bf0[4][4];    // step-0 fragment buffers
    uint32_t af1[MT][4], bf1[4][4];    // step-1 fragment buffers

    auto ldsm_all = [&](uint32_t stg, uint32_t kb2, uint32_t (*af)[4], uint32_t (*bf)[4]) {
        #pragma unroll
        for (int mt = 0; mt < MT; mt++)
            LDSM4(af[mt], stg + a_lane + mt * (16 * ROW_B) + kb2);
        #pragma unroll
        for (int p = 0; p < 4; p++)
            LDSM4(bf[p], stg + b_lane + p * (16 * ROW_B) + kb2);
    };
    auto hmma_all = [&](uint32_t (*af)[4], uint32_t (*bf)[4]) {
        #pragma unroll
        for (int mt = 0; mt < MT; mt++)
            #pragma unroll
            for (int p = 0; p < 4; p++) {
                mma_bf16(acc[mt][2 * p + 0], af[mt], &bf[p][0]);
                mma_bf16(acc[mt][2 * p + 1], af[mt], &bf[p][2]);
            }
    };

    // prologue: 3 stages in flight, frags for (kc=0, step0) resident
    load_stage(0, 0);
    load_stage(1, 1);
    load_stage(2, 2);
    asm volatile("cp.async.wait_group 2;" ::: "memory");
    __syncthreads();
    ldsm_all(sbase, 0, af0, bf0);

    for (int kc = 0; kc < KTILES; kc++) {
        const uint32_t stg = sbase + (uint32_t)(kc % STAGES) * STAGE_BYTES;

        // step 0: prefetch step-1 frags, then consume step-0 frags (32 HMMA)
        ldsm_all(stg, 32, af1, bf1);                    // k16 #1 (32 B offset)
        hmma_all(af0, bf0);

        // stage machinery + cross-kc fragment prefetch (hidden under HMMAs)
        if (kc + 3 < KTILES) {
            load_stage((kc + 3) % STAGES, kc + 3);
            asm volatile("cp.async.wait_group 2;" ::: "memory");
        } else if (kc + 2 < KTILES) {
            asm volatile("cp.async.wait_group 1;" ::: "memory");
        } else if (kc + 1 < KTILES) {
            asm volatile("cp.async.wait_group 0;" ::: "memory");
        }
        if (kc + 1 < KTILES) {
            __syncthreads();                            // stage kc+1 ready & safe
            ldsm_all(sbase + (uint32_t)((kc + 1) % STAGES) * STAGE_BYTES, 0, af0, bf0);
        }

        // step 1: consume step-1 frags (32 HMMA)
        hmma_all(af1, bf1);
    }
    __syncthreads();

    // ---- epilogue tables in freed smem ----
    float2* stab = reinterpret_cast<float2*>(smem);        // [BN][NUM_BINS] = 32 KB
    float*  ptab = smem + BN * NUM_BINS * 2;               // [BN]
    float*  btab = ptab + BN;                              // [BN]
    {
        int fg = f0 + tid;                                 // 256 threads, one f each
        float s1 = 0.0f, s2 = 0.0f;
        float2* row = stab + tid * NUM_BINS;
        #pragma unroll
        for (int k = 0; k < NUM_BINS; k++) {
            float h  = heights[fg * NUM_BINS + k];
            float wv = (h > 20.0f) ? h : log1pf(expf(h));  // softplus
            s1 += wv;
            s2 += (float)k * (1.0f / 15.0f) * wv;
            row[k] = make_float2(s1, s2);
        }
        ptab[tid] = phase[fg];
        btab[tid] = bias[fg];
    }
    __syncthreads();

    // ---- fused epilogue: sin -> sigmoid -> spline -> bias -> RoPE ----
    const int offset = *offset_p;

    #pragma unroll
    for (int mt = 0; mt < MT; mt++) {
        #pragma unroll
        for (int o = 0; o < 2; o++) {
            const int m = m0 + wm * 64 + mt * 16 + o * 8 + lr;
            const int nseq  = m & (SEQ_N - 1);
            const float tf0 = (float)(nseq + offset);
            const float days  = floorf(tf0 * (1.0f / (float)DAY_LENGTH));
            const float hours = tf0 - days * (float)DAY_LENGTH;

            #pragma unroll
            for (int nt = 0; nt < NT; nt++) {
                const int fl = wn * 64 + nt * 8 + lc * 2;  // even local f
                float vv[2];
                #pragma unroll
                for (int e = 0; e < 2; e++) {
                    float basis = acc[mt][nt][o * 2 + e] + ptab[fl + e];
                    float s = __sinf(basis);
                    float u = __fdividef(1.0f, 1.0f + __expf(-s));
                    int bin = (int)(u * 15.0f);
                    bin = bin < 0 ? 0 : (bin > 15 ? 15 : bin);
                    float2 S = stab[(fl + e) * NUM_BINS + bin];
                    vv[e] = fmaf(u, S.x, -S.y) + btab[fl + e];
                }
                float hv = (float)(f0 + fl) * (1.0f / (float)DIM);
                float invh = exp2f(-13.287712379549449f * hv);   // 10000^-half
                float invd = exp2f(-16.609640474436812f * hv);   // 100000^-half
                float sn, cs;
                __sincosf(fmaf(hours, invh, days * invd), &sn, &cs);
                float2 o2;
                o2.x = vv[0] * cs - vv[1] * sn;
                o2.y = vv[0] * sn + vv[1] * cs;
                *reinterpret_cast<float2*>(out + (size_t)m * DIM + f0 + fl) = o2;
            }
        }
    }
}

// ---------------- launch ----------------
extern "C" void kernel_launch(void* const* d_in, const int* in_sizes, int n_in,
                              void* d_out, int out_size)
{
    const float* x       = (const float*)d_in[0];
    const float* freqs   = (const float*)d_in[1];
    const float* phase   = (const float*)d_in[2];
    const float* heights = (const float*)d_in[3];
    const float* bias    = (const float*)d_in[4];
    const int*   offset  = (const int*)d_in[5];
    float*       out     = (float*)d_out;

    const int M = in_sizes[0] / IN_DIM;              // 16384

    const int xn4  = M * IN_DIM / 4;                 // 3,145,728
    const int tot4 = xn4 + DIM * IN_DIM / 4;         // +98,304
    const int cvt_blocks = (tot4 + 256 * CVT_UNROLL - 1) / (256 * CVT_UNROLL);
    cvt_kernel<<<cvt_blocks, 256>>>((const float4*)x, (const float4*)freqs, xn4, tot4);

    // Stateless + graph-capture safe (not a stream op).
    cudaFuncSetAttribute(atom_bf16_kernel,
                         cudaFuncAttributeMaxDynamicSharedMemorySize, SMEM_BYTES);

    dim3 grid(DIM / BN, M / BM);                     // (2, 128)
    atom_bf16_kernel<<<grid, NTHREADS, SMEM_BYTES>>>(phase, heights, bias,
                                                     offset, out);
}

// round 10
// speedup vs baseline: 1.5508x; 1.0766x over previous
#include <cuda_runtime.h>
#include <cuda_bf16.h>
#include <math.h>
#include <stdint.h>

// ---------------- problem constants ----------------
#define IN_DIM     768
#define DIM        512
#define NUM_BINS   16
#define SEQ_N      2048
#define DAY_LENGTH 64
#define M_TOTAL    16384

// ---------------- tiling ----------------
#define BM       128
#define BN       128
#define BK       32            // halves of K per stage
#define STAGES   4
#define NTHREADS 256
#define KTILES   (IN_DIM / BK) // 24

// 8 warps: 4 (M) x 2 (N), warp tile 32x64
#define MT 2                   // 2 x m16
#define NT 8                   // 8 x n8

// smem: bf16 rows of 40 halves (80 B) -> ldmatrix rows hit all 32 banks once
#define ROW_B       80
#define A_ROWS      BM
#define B_ROWS      BN
#define STAGE_BYTES ((A_ROWS + B_ROWS) * ROW_B)   // 20480
#define SMEM_BYTES  (STAGES * STAGE_BYTES)        // 81920  -> 2 CTAs/SM

// bf16 scratch (device globals -- no allocation)
__device__ __align__(16) __nv_bfloat16 g_xb[(size_t)M_TOTAL * IN_DIM];
__device__ __align__(16) __nv_bfloat16 g_fb[(size_t)DIM * IN_DIM];

__device__ __forceinline__ uint32_t smem_u32(const void* p) {
    uint32_t a;
    asm("{ .reg .u64 t; cvta.to.shared.u64 t, %1; cvt.u32.u64 %0, t; }" : "=r"(a) : "l"(p));
    return a;
}
__device__ __forceinline__ void cp16(uint32_t dst, const void* src) {
    asm volatile("cp.async.cg.shared.global [%0], [%1], 16;" :: "r"(dst), "l"(src) : "memory");
}
#define LDSM4(r, addr)                                                          \
    asm volatile("ldmatrix.sync.aligned.m8n8.x4.shared.b16 {%0,%1,%2,%3}, [%4];"\
        : "=r"((r)[0]), "=r"((r)[1]), "=r"((r)[2]), "=r"((r)[3]) : "r"(addr))

__device__ __forceinline__ void mma_bf16(float* c, const uint32_t* a, const uint32_t* b) {
    asm volatile(
        "mma.sync.aligned.m16n8k16.row.col.f32.bf16.bf16.f32 "
        "{%0,%1,%2,%3}, {%4,%5,%6,%7}, {%8,%9}, {%0,%1,%2,%3};"
        : "+f"(c[0]), "+f"(c[1]), "+f"(c[2]), "+f"(c[3])
        : "r"(a[0]), "r"(a[1]), "r"(a[2]), "r"(a[3]), "r"(b[0]), "r"(b[1]));
}

// ---------------- merged prepass: fp32 -> bf16, MLP=8 ----------------
#define CVT_UNROLL 8
__global__ void cvt_kernel(const float4* __restrict__ x,
                           const float4* __restrict__ fr,
                           int xn4, int tot4) {
    int base = blockIdx.x * (blockDim.x * CVT_UNROLL) + threadIdx.x;
    #pragma unroll
    for (int j = 0; j < CVT_UNROLL; j++) {
        int i = base + j * blockDim.x;
        if (i < xn4) {
            float4 v = x[i];
            __nv_bfloat162 lo = __floats2bfloat162_rn(v.x, v.y);
            __nv_bfloat162 hi = __floats2bfloat162_rn(v.z, v.w);
            uint2 o;
            o.x = *reinterpret_cast<uint32_t*>(&lo);
            o.y = *reinterpret_cast<uint32_t*>(&hi);
            reinterpret_cast<uint2*>(g_xb)[i] = o;
        } else if (i < tot4) {
            float4 v = fr[i - xn4];
            __nv_bfloat162 lo = __floats2bfloat162_rn(v.x, v.y);
            __nv_bfloat162 hi = __floats2bfloat162_rn(v.z, v.w);
            uint2 o;
            o.x = *reinterpret_cast<uint32_t*>(&lo);
            o.y = *reinterpret_cast<uint32_t*>(&hi);
            reinterpret_cast<uint2*>(g_fb)[i - xn4] = o;
        }
    }
}

// ---------------- main fused kernel (2 CTAs/SM) ----------------
__global__ __launch_bounds__(NTHREADS, 2)
void atom_bf16_kernel(const float* __restrict__ phase,    // [DIM]
                      const float* __restrict__ heights,  // [DIM, NUM_BINS]
                      const float* __restrict__ bias,     // [DIM]
                      const int*   __restrict__ offset_p,
                      float*       __restrict__ out)      // [M, DIM]
{
    extern __shared__ float smem[];
    const uint32_t sbase = smem_u32(smem);
    const int tid  = threadIdx.x;
    const int wid  = tid >> 5;
    const int lane = tid & 31;
    const int wm   = wid & 3;          // 4 x 32 = 128 M
    const int wn   = wid >> 2;         // 2 x 64 = 128 N
    const int f0   = blockIdx.x * BN;
    const int m0   = blockIdx.y * BM;
    const int lr   = lane >> 2;        // 0..7
    const int lc   = lane & 3;         // 0..3

    // ldmatrix per-lane base offsets (within a stage)
    const int lrow = lane & 7, lmat = lane >> 3;
    const uint32_t a_lane = (uint32_t)((wm * 32 + (lmat & 1) * 8 + lrow) * ROW_B
                                       + ((lmat >> 1) * 8) * 2);
    const uint32_t b_lane = (uint32_t)(A_ROWS * ROW_B
                                       + (wn * 64 + (lmat >> 1) * 8 + lrow) * ROW_B
                                       + ((lmat & 1) * 8) * 2);

    float acc[MT][NT][4];
    #pragma unroll
    for (int i = 0; i < MT; i++)
        #pragma unroll
        for (int j = 0; j < NT; j++)
            #pragma unroll
            for (int q = 0; q < 4; q++) acc[i][j][q] = 0.0f;

    auto load_stage = [&](int s, int kc) {
        const uint32_t base = sbase + (uint32_t)s * STAGE_BYTES;
        const __nv_bfloat16* ag = g_xb + (size_t)m0 * IN_DIM + kc * BK;
        #pragma unroll
        for (int j = 0; j < 2; j++) {   // A: 128 rows x 4 chunks of 16B = 512
            int idx = tid + j * NTHREADS;
            int row = idx >> 2, c = idx & 3;
            cp16(base + row * ROW_B + c * 16, ag + (size_t)row * IN_DIM + c * 8);
        }
        const __nv_bfloat16* bg = g_fb + (size_t)f0 * IN_DIM + kc * BK;
        const uint32_t bbase = base + A_ROWS * ROW_B;
        #pragma unroll
        for (int j = 0; j < 2; j++) {   // B: 128 rows x 4 chunks = 512
            int idx = tid + j * NTHREADS;
            int row = idx >> 2, c = idx & 3;
            cp16(bbase + row * ROW_B + c * 16, bg + (size_t)row * IN_DIM + c * 8);
        }
        asm volatile("cp.async.commit_group;" ::: "memory");
    };

    uint32_t af[MT][4], bf[4][4];   // single-buffered fragments (reg budget!)

    auto ldsm_all = [&](uint32_t stg, uint32_t kb2) {
        #pragma unroll
        for (int mt = 0; mt < MT; mt++)
            LDSM4(af[mt], stg + a_lane + mt * (16 * ROW_B) + kb2);
        #pragma unroll
        for (int p = 0; p < 4; p++)
            LDSM4(bf[p], stg + b_lane + p * (16 * ROW_B) + kb2);
    };
    auto hmma_all = [&]() {
        #pragma unroll
        for (int mt = 0; mt < MT; mt++)
            #pragma unroll
            for (int p = 0; p < 4; p++) {
                mma_bf16(acc[mt][2 * p + 0], af[mt], &bf[p][0]);
                mma_bf16(acc[mt][2 * p + 1], af[mt], &bf[p][2]);
            }
    };

    // prologue: 3 stages in flight
    load_stage(0, 0);
    load_stage(1, 1);
    load_stage(2, 2);
    asm volatile("cp.async.wait_group 2;" ::: "memory");
    __syncthreads();

    for (int kc = 0; kc < KTILES; kc++) {
        const uint32_t stg = sbase + (uint32_t)(kc % STAGES) * STAGE_BYTES;

        ldsm_all(stg, 0);               // k16 step 0
        hmma_all();
        if (kc + 3 < KTILES)            // overlap next-stage issue with step 1
            load_stage((kc + 3) % STAGES, kc + 3);
        ldsm_all(stg, 32);              // k16 step 1 (32 B offset)
        hmma_all();

        if (kc + 3 < KTILES)      asm volatile("cp.async.wait_group 2;" ::: "memory");
        else if (kc + 2 < KTILES) asm volatile("cp.async.wait_group 1;" ::: "memory");
        else if (kc + 1 < KTILES) asm volatile("cp.async.wait_group 0;" ::: "memory");
        if (kc + 1 < KTILES) __syncthreads();
    }
    __syncthreads();

    // ---- epilogue tables in freed smem ----
    float2* stab = reinterpret_cast<float2*>(smem);        // [BN][NUM_BINS] = 16 KB
    float*  ptab = smem + BN * NUM_BINS * 2;               // [BN]
    float*  btab = ptab + BN;                              // [BN]
    if (tid < BN) {
        int fg = f0 + tid;
        float s1 = 0.0f, s2 = 0.0f;
        float2* row = stab + tid * NUM_BINS;
        #pragma unroll
        for (int k = 0; k < NUM_BINS; k++) {
            float h  = heights[fg * NUM_BINS + k];
            float wv = (h > 20.0f) ? h : log1pf(expf(h));  // softplus
            s1 += wv;
            s2 += (float)k * (1.0f / 15.0f) * wv;
            row[k] = make_float2(s1, s2);
        }
        ptab[tid] = phase[fg];
        btab[tid] = bias[fg];
    }
    __syncthreads();

    // ---- fused epilogue: sin -> sigmoid -> spline -> bias -> RoPE ----
    const int offset = *offset_p;

    #pragma unroll
    for (int mt = 0; mt < MT; mt++) {
        #pragma unroll
        for (int o = 0; o < 2; o++) {
            const int m = m0 + wm * 32 + mt * 16 + o * 8 + lr;
            const int nseq  = m & (SEQ_N - 1);
            const float tf0 = (float)(nseq + offset);
            const float days  = floorf(tf0 * (1.0f / (float)DAY_LENGTH));
            const float hours = tf0 - days * (float)DAY_LENGTH;

            #pragma unroll
            for (int nt = 0; nt < NT; nt++) {
                const int fl = wn * 64 + nt * 8 + lc * 2;  // even local f
                float vv[2];
                #pragma unroll
                for (int e = 0; e < 2; e++) {
                    float basis = acc[mt][nt][o * 2 + e] + ptab[fl + e];
                    float s = __sinf(basis);
                    float u = __fdividef(1.0f, 1.0f + __expf(-s));
                    int bin = (int)(u * 15.0f);
                    bin = bin < 0 ? 0 : (bin > 15 ? 15 : bin);
                    float2 S = stab[(fl + e) * NUM_BINS + bin];
                    vv[e] = fmaf(u, S.x, -S.y) + btab[fl + e];
                }
                float hv = (float)(f0 + fl) * (1.0f / (float)DIM);
                float invh = exp2f(-13.287712379549449f * hv);   // 10000^-half
                float invd = exp2f(-16.609640474436812f * hv);   // 100000^-half
                float sn, cs;
                __sincosf(fmaf(hours, invh, days * invd), &sn, &cs);
                float2 o2;
                o2.x = vv[0] * cs - vv[1] * sn;
                o2.y = vv[0] * sn + vv[1] * cs;
                *reinterpret_cast<float2*>(out + (size_t)m * DIM + f0 + fl) = o2;
            }
        }
    }
}

// ---------------- launch ----------------
extern "C" void kernel_launch(void* const* d_in, const int* in_sizes, int n_in,
                              void* d_out, int out_size)
{
    const float* x       = (const float*)d_in[0];
    const float* freqs   = (const float*)d_in[1];
    const float* phase   = (const float*)d_in[2];
    const float* heights = (const float*)d_in[3];
    const float* bias    = (const float*)d_in[4];
    const int*   offset  = (const int*)d_in[5];
    float*       out     = (float*)d_out;

    const int M = in_sizes[0] / IN_DIM;              // 16384

    const int xn4  = M * IN_DIM / 4;                 // 3,145,728
    const int tot4 = xn4 + DIM * IN_DIM / 4;         // +98,304
    const int cvt_blocks = (tot4 + 256 * CVT_UNROLL - 1) / (256 * CVT_UNROLL);
    cvt_kernel<<<cvt_blocks, 256>>>((const float4*)x, (const float4*)freqs, xn4, tot4);

    // Stateless + graph-capture safe (not a stream op).
    cudaFuncSetAttribute(atom_bf16_kernel,
                         cudaFuncAttributeMaxDynamicSharedMemorySize, SMEM_BYTES);

    dim3 grid(DIM / BN, M / BM);                     // (4, 128) = 512 CTAs
    atom_bf16_kernel<<<grid, NTHREADS, SMEM_BYTES>>>(phase, heights, bias,
                                                     offset, out);
}